// round 8
// baseline (speedup 1.0000x reference)
#include <cuda_runtime.h>
#include <cuda_fp16.h>

#define NN 8192
#define CC 16
#define KAUG 40          // halves per augmented row (24 used), 80B stride
#define UPAD 136
#define THREADS 256
#define NTILES 4         // j-tiles of 128 per CTA (grid.y = 16)

// ---------------- device scratch ----------------
__device__ __align__(16) __half g_Aaug[NN * KAUG];
__device__ __align__(16) __half g_Baug[NN * KAUG];
__device__ __align__(16) __half g_UT[64 * CC * 128];   // [tile][c][j]

// smem layout (in halves)
#define SA  0
#define SB0 10240
#define SB1 15360
#define SU0 20480
#define SU1 22656
#define SMEM_HALVES 24832
#define SMEM_BYTES (SMEM_HALVES * 2)

// ---------------- helpers ----------------
__device__ __forceinline__ unsigned s2u(const void* p) {
    return (unsigned)__cvta_generic_to_shared(p);
}
__device__ __forceinline__ unsigned cvt2h(float hi, float lo) {
    unsigned d; asm("cvt.rn.f16x2.f32 %0, %1, %2;" : "=r"(d) : "f"(hi), "f"(lo)); return d;
}
__device__ __forceinline__ unsigned ex2h(unsigned x) {
    unsigned y; asm("ex2.approx.f16x2 %0, %1;" : "=r"(y) : "r"(x)); return y;
}
__device__ __forceinline__ void ldsm4(unsigned& r0, unsigned& r1, unsigned& r2, unsigned& r3, unsigned a) {
    asm volatile("ldmatrix.sync.aligned.m8n8.x4.shared.b16 {%0,%1,%2,%3}, [%4];"
                 : "=r"(r0), "=r"(r1), "=r"(r2), "=r"(r3) : "r"(a));
}
__device__ __forceinline__ void mma16816(float* c, unsigned a0, unsigned a1, unsigned a2, unsigned a3,
                                         unsigned b0, unsigned b1) {
    asm volatile("mma.sync.aligned.m16n8k16.row.col.f32.f16.f16.f32 "
                 "{%0,%1,%2,%3}, {%4,%5,%6,%7}, {%8,%9}, {%0,%1,%2,%3};"
                 : "+f"(c[0]), "+f"(c[1]), "+f"(c[2]), "+f"(c[3])
                 : "r"(a0), "r"(a1), "r"(a2), "r"(a3), "r"(b0), "r"(b1));
}
__device__ __forceinline__ void cp16(unsigned saddr, const void* g) {
    asm volatile("cp.async.ca.shared.global [%0], [%1], 16;" :: "r"(saddr), "l"(g));
}
#define CP_COMMIT() asm volatile("cp.async.commit_group;" ::: "memory")

// ---------------- pre-kernel: 128 blocks x 256 threads, 64 rows each ----------------
__global__ __launch_bounds__(256) void lg_pre_kernel(const float* __restrict__ U,
                                                     const float* __restrict__ ref,
                                                     float* __restrict__ out) {
    __shared__ __half sUh[64 * 17];
    const int b = blockIdx.x;
    const int tid = threadIdx.x;

    // part 1: 64 rows of U -> out=-U, stage f16 (coalesced)
#pragma unroll
    for (int k = 0; k < 4; k++) {
        int idx = k * 256 + tid;               // 0..1023 over 64 rows x 16 cols
        float f = U[b * 1024 + idx];
        out[b * 1024 + idx] = -f;
        sUh[(idx >> 4) * 17 + (idx & 15)] = __float2half_rn(f);
    }
    __syncthreads();

    // part 2: half a U^T tile (16 c x 32 j2) per block
    {
        unsigned* gUTu = (unsigned*)g_UT;
        const int T = b >> 1;
        const int jhalf = (b & 1) * 32;
#pragma unroll
        for (int k = 0; k < 2; k++) {
            int w = k * 256 + tid;             // 0..511
            int c  = w >> 5;
            int j2l = w & 31;
            int lr = 2 * j2l;
            __half h0 = sUh[lr * 17 + c];
            __half h1 = sUh[(lr + 1) * 17 + c];
            unsigned v = (unsigned)__half_as_ushort(h0) | ((unsigned)__half_as_ushort(h1) << 16);
            gUTu[((size_t)T * 16 + c) * 64 + jhalf + j2l] = v;
        }
    }

    // part 3: augmented split-fp16 A/B rows (64 rows, tid<64)
    if (tid < 64) {
        const int i = b * 64 + tid;
        const float SC = 1.2011224087864498f;  // sqrt(log2 e)
        float rs[5], ss = 0.f;
#pragma unroll
        for (int k = 0; k < 5; k++) { rs[k] = ref[i * 5 + k] * SC; ss += rs[k] * rs[k]; }
        float c = -0.5f * ss;
        unsigned short rh[5], rl[5], chh, cll;
#pragma unroll
        for (int k = 0; k < 5; k++) {
            __half hh = __float2half_rn(rs[k]);
            rh[k] = __half_as_ushort(hh);
            rl[k] = __half_as_ushort(__float2half_rn(rs[k] - __half2float(hh)));
        }
        {
            __half hc = __float2half_rn(c);
            chh = __half_as_ushort(hc);
            cll = __half_as_ushort(__float2half_rn(c - __half2float(hc)));
        }
        const unsigned short ONE = 0x3C00;
        unsigned short A[KAUG], B[KAUG];
#pragma unroll
        for (int k = 0; k < KAUG; k++) { A[k] = 0; B[k] = 0; }
        // A: k0-7=[rh,ch,1,0]  k8-15=[rl,cl,0,0]  k16-23=[rh,ch,1,0]
#pragma unroll
        for (int k = 0; k < 5; k++) { A[k] = rh[k]; A[8 + k] = rl[k]; A[16 + k] = rh[k]; }
        A[5] = chh; A[6] = ONE; A[13] = cll; A[21] = chh; A[22] = ONE;
        // B: k0-7=[rh,1,ch,0]  k8-15=same  k16-23=[rl,0,cl,0]
#pragma unroll
        for (int k = 0; k < 5; k++) { B[k] = rh[k]; B[8 + k] = rh[k]; B[16 + k] = rl[k]; }
        B[5] = ONE; B[6] = chh; B[13] = ONE; B[14] = chh; B[22] = cll;
        uint4* gA = (uint4*)(g_Aaug + (size_t)i * KAUG);
        uint4* gB = (uint4*)(g_Baug + (size_t)i * KAUG);
#pragma unroll
        for (int q = 0; q < 5; q++) {
            gA[q] = ((const uint4*)A)[q];
            gB[q] = ((const uint4*)B)[q];
        }
    }
}

// ---------------- main kernel: i-tile 256 (m32 per warp), 4 CTAs/SM ----------------
__global__ __launch_bounds__(THREADS, 4) void lg_main_kernel(float* __restrict__ out) {
    extern __shared__ __align__(16) __half smem[];

    const int tid = threadIdx.x;
    const int w = tid >> 5;
    const int l = tid & 31;
    const int bx = blockIdx.x;
    const int by = blockIdx.y;

    const unsigned sAb = s2u(smem + SA);
    const unsigned sBb0 = s2u(smem + SB0);
    const unsigned sBb1 = s2u(smem + SB1);
    const unsigned sUb0 = s2u(smem + SU0);
    const unsigned sUb1 = s2u(smem + SU1);

    // ---- prologue copies (cp.async) ----
    {
        const char* gA = (const char*)(g_Aaug) + (size_t)bx * 256 * KAUG * 2;
        for (int k = tid; k < 1280; k += THREADS) cp16(sAb + k * 16, gA + k * 16);
        const int jt0 = by * NTILES;
        const char* gB = (const char*)(g_Baug) + (size_t)jt0 * 128 * KAUG * 2;
        for (int k = tid; k < 640; k += THREADS) cp16(sBb0 + k * 16, gB + k * 16);
        const char* gU = (const char*)(g_UT) + (size_t)jt0 * CC * 256;
        for (int k = tid; k < 256; k += THREADS) {
            int row = k >> 4, q = k & 15;
            cp16(sUb0 + row * (UPAD * 2) + q * 16, gU + k * 16);
        }
        CP_COMMIT();
        const char* gB1 = (const char*)(g_Baug) + (size_t)(jt0 + 1) * 128 * KAUG * 2;
        for (int k = tid; k < 640; k += THREADS) cp16(sBb1 + k * 16, gB1 + k * 16);
        const char* gU1 = (const char*)(g_UT) + (size_t)(jt0 + 1) * CC * 256;
        for (int k = tid; k < 256; k += THREADS) {
            int row = k >> 4, q = k & 15;
            cp16(sUb1 + row * (UPAD * 2) + q * 16, gU1 + k * 16);
        }
        CP_COMMIT();
    }

    // lane address pieces
    const int lrowB = ((l >> 4) & 1) * 8 + (l & 7);
    const int lkB   = ((l >> 3) & 1) * 16;
    const int lrowA = ((l >> 3) & 1) * 8 + (l & 7);
    const int lkA   = ((l >> 4) & 1) * 16;

    const unsigned aAddr0 = sAb + (w * 32 + lrowA) * (KAUG * 2) + lkA;
    const unsigned aAddr1 = aAddr0 + 16 * (KAUG * 2);

    unsigned aF0[2][4], aF1[2][4];
    float o0[2][4], o1[2][4];
#pragma unroll
    for (int nb = 0; nb < 2; nb++)
#pragma unroll
        for (int q = 0; q < 4; q++) { o0[nb][q] = 0.f; o1[nb][q] = 0.f; }

    bool aLoaded = false;

    for (int t = 0; t < NTILES; t++) {
        if (t == NTILES - 1) asm volatile("cp.async.wait_group 0;" ::: "memory");
        else                 asm volatile("cp.async.wait_group 1;" ::: "memory");
        __syncthreads();

        if (!aLoaded) {
            ldsm4(aF0[0][0], aF0[0][1], aF0[0][2], aF0[0][3], aAddr0);
            ldsm4(aF0[1][0], aF0[1][1], aF0[1][2], aF0[1][3], aAddr0 + 32);
            ldsm4(aF1[0][0], aF1[0][1], aF1[0][2], aF1[0][3], aAddr1);
            ldsm4(aF1[1][0], aF1[1][1], aF1[1][2], aF1[1][3], aAddr1 + 32);
            aLoaded = true;
        }

        const unsigned bBase = (t & 1) ? sBb1 : sBb0;
        const unsigned uBase = (t & 1) ? sUb1 : sUb0;

#pragma unroll
        for (int p = 0; p < 8; p++) {
            const unsigned addrB = bBase + (p * 16 + lrowB) * (KAUG * 2) + lkB;
            unsigned b0, b1, b2, b3, b4, b5, b6, b7;
            ldsm4(b0, b1, b2, b3, addrB);        // k-step 0
            ldsm4(b4, b5, b6, b7, addrB + 32);   // k-step 1

            unsigned w00, w01, w02, w03;
            {
                float s0[4] = {0.f, 0.f, 0.f, 0.f};
                float s1[4] = {0.f, 0.f, 0.f, 0.f};
                mma16816(s0, aF0[0][0], aF0[0][1], aF0[0][2], aF0[0][3], b0, b1);
                mma16816(s1, aF0[0][0], aF0[0][1], aF0[0][2], aF0[0][3], b2, b3);
                mma16816(s0, aF0[1][0], aF0[1][1], aF0[1][2], aF0[1][3], b4, b5);
                mma16816(s1, aF0[1][0], aF0[1][1], aF0[1][2], aF0[1][3], b6, b7);
                w00 = ex2h(cvt2h(s0[1], s0[0]));
                w01 = ex2h(cvt2h(s0[3], s0[2]));
                w02 = ex2h(cvt2h(s1[1], s1[0]));
                w03 = ex2h(cvt2h(s1[3], s1[2]));
            }
            unsigned w10, w11, w12, w13;
            {
                float s0[4] = {0.f, 0.f, 0.f, 0.f};
                float s1[4] = {0.f, 0.f, 0.f, 0.f};
                mma16816(s0, aF1[0][0], aF1[0][1], aF1[0][2], aF1[0][3], b0, b1);
                mma16816(s1, aF1[0][0], aF1[0][1], aF1[0][2], aF1[0][3], b2, b3);
                mma16816(s0, aF1[1][0], aF1[1][1], aF1[1][2], aF1[1][3], b4, b5);
                mma16816(s1, aF1[1][0], aF1[1][1], aF1[1][2], aF1[1][3], b6, b7);
                w10 = ex2h(cvt2h(s0[1], s0[0]));
                w11 = ex2h(cvt2h(s0[3], s0[2]));
                w12 = ex2h(cvt2h(s1[1], s1[0]));
                w13 = ex2h(cvt2h(s1[3], s1[2]));
            }

            unsigned u0, u1, u2, u3;
            ldsm4(u0, u1, u2, u3, uBase + lrowB * (UPAD * 2) + p * 32 + lkB);
            mma16816(o0[0], w00, w01, w02, w03, u0, u1);
            mma16816(o0[1], w00, w01, w02, w03, u2, u3);
            mma16816(o1[0], w10, w11, w12, w13, u0, u1);
            mma16816(o1[1], w10, w11, w12, w13, u2, u3);
        }

        __syncthreads();

        // ---- prefetch tile t+2 ----
        if (t + 2 < NTILES) {
            const int jt = by * NTILES + t + 2;
            const unsigned dB = (t & 1) ? sBb1 : sBb0;
            const unsigned dU = (t & 1) ? sUb1 : sUb0;
            const char* gB = (const char*)(g_Baug) + (size_t)jt * 128 * KAUG * 2;
            for (int k = tid; k < 640; k += THREADS) cp16(dB + k * 16, gB + k * 16);
            const char* gU = (const char*)(g_UT) + (size_t)jt * CC * 256;
            for (int k = tid; k < 256; k += THREADS) {
                int row = k >> 4, q = k & 15;
                cp16(dU + row * (UPAD * 2) + q * 16, gU + k * 16);
            }
            CP_COMMIT();
        } else {
            CP_COMMIT();
        }
    }

    // ---- epilogue ----
    const int g = l >> 2;
    const int tq = l & 3;
    const int i0 = bx * 256 + w * 32 + g;
#pragma unroll
    for (int nb = 0; nb < 2; nb++) {
        const int col = nb * 8 + tq * 2;
        atomicAdd(&out[i0 * CC + col],            o0[nb][0]);
        atomicAdd(&out[i0 * CC + col + 1],        o0[nb][1]);
        atomicAdd(&out[(i0 + 8) * CC + col],      o0[nb][2]);
        atomicAdd(&out[(i0 + 8) * CC + col + 1],  o0[nb][3]);
        atomicAdd(&out[(i0 + 16) * CC + col],     o1[nb][0]);
        atomicAdd(&out[(i0 + 16) * CC + col + 1], o1[nb][1]);
        atomicAdd(&out[(i0 + 24) * CC + col],     o1[nb][2]);
        atomicAdd(&out[(i0 + 24) * CC + col + 1], o1[nb][3]);
    }
}

extern "C" void kernel_launch(void* const* d_in, const int* in_sizes, int n_in,
                              void* d_out, int out_size) {
    const float* U   = (const float*)d_in[0];
    const float* ref = (const float*)d_in[1];
    float* out = (float*)d_out;

    static int attrSet = 0;
    if (!attrSet) {
        cudaFuncSetAttribute(lg_main_kernel, cudaFuncAttributeMaxDynamicSharedMemorySize, SMEM_BYTES);
        attrSet = 1;
    }

    lg_pre_kernel<<<128, 256>>>(U, ref, out);

    dim3 grid(NN / 256, 16);
    lg_main_kernel<<<grid, THREADS, SMEM_BYTES>>>(out);
}

// round 9
// speedup vs baseline: 1.2819x; 1.2819x over previous
#include <cuda_runtime.h>
#include <cuda_fp16.h>

#define NN 8192
#define CC 16
#define KAUG 40          // halves per augmented row (24 used), 80B stride
#define UPAD 136
#define THREADS 256

// ---------------- device scratch ----------------
__device__ __align__(16) __half g_Aaug[NN * KAUG];
__device__ __align__(16) __half g_Baug[NN * KAUG];
__device__ __align__(16) __half g_UT[64 * CC * 128];   // [tile][c][j]

// smem layout (in halves)
#define SA  0
#define SB  10240
#define SU  15360
#define SMEM_HALVES 17536
#define SMEM_BYTES (SMEM_HALVES * 2)   // 35072 B

// ---------------- helpers ----------------
__device__ __forceinline__ unsigned s2u(const void* p) {
    return (unsigned)__cvta_generic_to_shared(p);
}
__device__ __forceinline__ unsigned cvt2h(float hi, float lo) {
    unsigned d; asm("cvt.rn.f16x2.f32 %0, %1, %2;" : "=r"(d) : "f"(hi), "f"(lo)); return d;
}
__device__ __forceinline__ unsigned ex2h(unsigned x) {
    unsigned y; asm("ex2.approx.f16x2 %0, %1;" : "=r"(y) : "r"(x)); return y;
}
__device__ __forceinline__ void ldsm4(unsigned& r0, unsigned& r1, unsigned& r2, unsigned& r3, unsigned a) {
    asm volatile("ldmatrix.sync.aligned.m8n8.x4.shared.b16 {%0,%1,%2,%3}, [%4];"
                 : "=r"(r0), "=r"(r1), "=r"(r2), "=r"(r3) : "r"(a));
}
__device__ __forceinline__ void mma16816(float* c, unsigned a0, unsigned a1, unsigned a2, unsigned a3,
                                         unsigned b0, unsigned b1) {
    asm volatile("mma.sync.aligned.m16n8k16.row.col.f32.f16.f16.f32 "
                 "{%0,%1,%2,%3}, {%4,%5,%6,%7}, {%8,%9}, {%0,%1,%2,%3};"
                 : "+f"(c[0]), "+f"(c[1]), "+f"(c[2]), "+f"(c[3])
                 : "r"(a0), "r"(a1), "r"(a2), "r"(a3), "r"(b0), "r"(b1));
}
__device__ __forceinline__ void cp16(unsigned saddr, const void* g) {
    asm volatile("cp.async.ca.shared.global [%0], [%1], 16;" :: "r"(saddr), "l"(g));
}
#define CP_COMMIT() asm volatile("cp.async.commit_group;" ::: "memory")

// ---------------- pre-kernel: 64 blocks x 256 threads, 128 rows each (R6 version) ----------------
__global__ __launch_bounds__(256) void lg_pre_kernel(const float* __restrict__ U,
                                                     const float* __restrict__ ref,
                                                     float* __restrict__ out) {
    __shared__ __half sUh[128 * 17];
    const int b = blockIdx.x;
    const int tid = threadIdx.x;

#pragma unroll
    for (int k = 0; k < 8; k++) {
        int idx = k * 256 + tid;
        float f = U[b * 2048 + idx];
        out[b * 2048 + idx] = -f;
        sUh[(idx >> 4) * 17 + (idx & 15)] = __float2half_rn(f);
    }
    __syncthreads();

    unsigned* gUTu = (unsigned*)g_UT;
#pragma unroll
    for (int k = 0; k < 4; k++) {
        int w = k * 256 + tid;
        int c  = w >> 6;
        int j2 = w & 63;
        __half h0 = sUh[(2 * j2) * 17 + c];
        __half h1 = sUh[(2 * j2 + 1) * 17 + c];
        unsigned v = (unsigned)__half_as_ushort(h0) | ((unsigned)__half_as_ushort(h1) << 16);
        gUTu[((size_t)b * 16 + c) * 64 + j2] = v;
    }

    if (tid < 128) {
        const int i = b * 128 + tid;
        const float SC = 1.2011224087864498f;  // sqrt(log2 e)
        float rs[5], ss = 0.f;
#pragma unroll
        for (int k = 0; k < 5; k++) { rs[k] = ref[i * 5 + k] * SC; ss += rs[k] * rs[k]; }
        float c = -0.5f * ss;
        unsigned short rh[5], rl[5], chh, cll;
#pragma unroll
        for (int k = 0; k < 5; k++) {
            __half hh = __float2half_rn(rs[k]);
            rh[k] = __half_as_ushort(hh);
            rl[k] = __half_as_ushort(__float2half_rn(rs[k] - __half2float(hh)));
        }
        {
            __half hc = __float2half_rn(c);
            chh = __half_as_ushort(hc);
            cll = __half_as_ushort(__float2half_rn(c - __half2float(hc)));
        }
        const unsigned short ONE = 0x3C00;
        unsigned short A[KAUG], B[KAUG];
#pragma unroll
        for (int k = 0; k < KAUG; k++) { A[k] = 0; B[k] = 0; }
        // A: k0-7=[rh,ch,1,0]  k8-15=[rl,cl,0,0]  k16-23=[rh,ch,1,0]
#pragma unroll
        for (int k = 0; k < 5; k++) { A[k] = rh[k]; A[8 + k] = rl[k]; A[16 + k] = rh[k]; }
        A[5] = chh; A[6] = ONE; A[13] = cll; A[21] = chh; A[22] = ONE;
        // B: k0-7=[rh,1,ch,0]  k8-15=same  k16-23=[rl,0,cl,0]
#pragma unroll
        for (int k = 0; k < 5; k++) { B[k] = rh[k]; B[8 + k] = rh[k]; B[16 + k] = rl[k]; }
        B[5] = ONE; B[6] = chh; B[13] = ONE; B[14] = chh; B[22] = cll;
        uint4* gA = (uint4*)(g_Aaug + (size_t)i * KAUG);
        uint4* gB = (uint4*)(g_Baug + (size_t)i * KAUG);
#pragma unroll
        for (int q = 0; q < 5; q++) {
            gA[q] = ((const uint4*)A)[q];
            gB[q] = ((const uint4*)B)[q];
        }
    }
}

// ---------------- main kernel: one (i256 x j128) tile per CTA ----------------
__global__ __launch_bounds__(THREADS, 3) void lg_main_kernel(float* __restrict__ out) {
    extern __shared__ __align__(16) __half smem[];

    const int tid = threadIdx.x;
    const int w = tid >> 5;
    const int l = tid & 31;
    const int bx = blockIdx.x;   // i-tile (256 rows)
    const int by = blockIdx.y;   // j-tile (128 rows)

    const unsigned sAb = s2u(smem + SA);
    const unsigned sBb = s2u(smem + SB);
    const unsigned sUb = s2u(smem + SU);

    // ---- prologue: load A, B, U tiles ----
    {
        const char* gA = (const char*)(g_Aaug) + (size_t)bx * 256 * KAUG * 2;
        for (int k = tid; k < 1280; k += THREADS) cp16(sAb + k * 16, gA + k * 16);
        const char* gB = (const char*)(g_Baug) + (size_t)by * 128 * KAUG * 2;
        for (int k = tid; k < 640; k += THREADS) cp16(sBb + k * 16, gB + k * 16);
        const char* gU = (const char*)(g_UT) + (size_t)by * CC * 256;
        for (int k = tid; k < 256; k += THREADS) {
            int row = k >> 4, q = k & 15;
            cp16(sUb + row * (UPAD * 2) + q * 16, gU + k * 16);
        }
        CP_COMMIT();
    }

    // lane address pieces
    const int lrowB = ((l >> 4) & 1) * 8 + (l & 7);
    const int lkB   = ((l >> 3) & 1) * 16;
    const int lrowA = ((l >> 3) & 1) * 8 + (l & 7);
    const int lkA   = ((l >> 4) & 1) * 16;

    const unsigned aAddr0 = sAb + (w * 32 + lrowA) * (KAUG * 2) + lkA;
    const unsigned aAddr1 = aAddr0 + 16 * (KAUG * 2);

    float o0[2][4], o1[2][4];
#pragma unroll
    for (int nb = 0; nb < 2; nb++)
#pragma unroll
        for (int q = 0; q < 4; q++) { o0[nb][q] = 0.f; o1[nb][q] = 0.f; }

    asm volatile("cp.async.wait_group 0;" ::: "memory");
    __syncthreads();

    unsigned aF0[2][4], aF1[2][4];
    ldsm4(aF0[0][0], aF0[0][1], aF0[0][2], aF0[0][3], aAddr0);
    ldsm4(aF0[1][0], aF0[1][1], aF0[1][2], aF0[1][3], aAddr0 + 32);
    ldsm4(aF1[0][0], aF1[0][1], aF1[0][2], aF1[0][3], aAddr1);
    ldsm4(aF1[1][0], aF1[1][1], aF1[1][2], aF1[1][3], aAddr1 + 32);

#pragma unroll
    for (int p = 0; p < 8; p++) {
        const unsigned addrB = sBb + (p * 16 + lrowB) * (KAUG * 2) + lkB;
        unsigned b0, b1, b2, b3, b4, b5, b6, b7;
        ldsm4(b0, b1, b2, b3, addrB);        // k-step 0
        ldsm4(b4, b5, b6, b7, addrB + 32);   // k-step 1

        unsigned w00, w01, w02, w03;
        {
            float s0[4] = {0.f, 0.f, 0.f, 0.f};
            float s1[4] = {0.f, 0.f, 0.f, 0.f};
            mma16816(s0, aF0[0][0], aF0[0][1], aF0[0][2], aF0[0][3], b0, b1);
            mma16816(s1, aF0[0][0], aF0[0][1], aF0[0][2], aF0[0][3], b2, b3);
            mma16816(s0, aF0[1][0], aF0[1][1], aF0[1][2], aF0[1][3], b4, b5);
            mma16816(s1, aF0[1][0], aF0[1][1], aF0[1][2], aF0[1][3], b6, b7);
            w00 = ex2h(cvt2h(s0[1], s0[0]));
            w01 = ex2h(cvt2h(s0[3], s0[2]));
            w02 = ex2h(cvt2h(s1[1], s1[0]));
            w03 = ex2h(cvt2h(s1[3], s1[2]));
        }
        unsigned w10, w11, w12, w13;
        {
            float s0[4] = {0.f, 0.f, 0.f, 0.f};
            float s1[4] = {0.f, 0.f, 0.f, 0.f};
            mma16816(s0, aF1[0][0], aF1[0][1], aF1[0][2], aF1[0][3], b0, b1);
            mma16816(s1, aF1[0][0], aF1[0][1], aF1[0][2], aF1[0][3], b2, b3);
            mma16816(s0, aF1[1][0], aF1[1][1], aF1[1][2], aF1[1][3], b4, b5);
            mma16816(s1, aF1[1][0], aF1[1][1], aF1[1][2], aF1[1][3], b6, b7);
            w10 = ex2h(cvt2h(s0[1], s0[0]));
            w11 = ex2h(cvt2h(s0[3], s0[2]));
            w12 = ex2h(cvt2h(s1[1], s1[0]));
            w13 = ex2h(cvt2h(s1[3], s1[2]));
        }

        unsigned u0, u1, u2, u3;
        ldsm4(u0, u1, u2, u3, sUb + lrowB * (UPAD * 2) + p * 32 + lkB);
        mma16816(o0[0], w00, w01, w02, w03, u0, u1);
        mma16816(o0[1], w00, w01, w02, w03, u2, u3);
        mma16816(o1[0], w10, w11, w12, w13, u0, u1);
        mma16816(o1[1], w10, w11, w12, w13, u2, u3);
    }

    // ---- epilogue ----
    const int g = l >> 2;
    const int tq = l & 3;
    const int i0 = bx * 256 + w * 32 + g;
#pragma unroll
    for (int nb = 0; nb < 2; nb++) {
        const int col = nb * 8 + tq * 2;
        atomicAdd(&out[i0 * CC + col],            o0[nb][0]);
        atomicAdd(&out[i0 * CC + col + 1],        o0[nb][1]);
        atomicAdd(&out[(i0 + 8) * CC + col],      o0[nb][2]);
        atomicAdd(&out[(i0 + 8) * CC + col + 1],  o0[nb][3]);
        atomicAdd(&out[(i0 + 16) * CC + col],     o1[nb][0]);
        atomicAdd(&out[(i0 + 16) * CC + col + 1], o1[nb][1]);
        atomicAdd(&out[(i0 + 24) * CC + col],     o1[nb][2]);
        atomicAdd(&out[(i0 + 24) * CC + col + 1], o1[nb][3]);
    }
}

extern "C" void kernel_launch(void* const* d_in, const int* in_sizes, int n_in,
                              void* d_out, int out_size) {
    const float* U   = (const float*)d_in[0];
    const float* ref = (const float*)d_in[1];
    float* out = (float*)d_out;

    static int attrSet = 0;
    if (!attrSet) {
        cudaFuncSetAttribute(lg_main_kernel, cudaFuncAttributeMaxDynamicSharedMemorySize, SMEM_BYTES);
        attrSet = 1;
    }

    lg_pre_kernel<<<64, 256>>>(U, ref, out);

    dim3 grid(NN / 256, NN / 128);
    lg_main_kernel<<<grid, THREADS, SMEM_BYTES>>>(out);
}